// round 10
// baseline (speedup 1.0000x reference)
#include <cuda_runtime.h>
#include <cuda_bf16.h>
#include <stdint.h>

// out[B=1024, W=201000] f32 one-hot triple scatter over zeros.
// Inputs: z f32 (unused), hID i32[1024], rID i32[1024], tID i32[1024].
//
// Structure:
//   node A: cudaMemsetAsync (CE fill path, ~7.9 TB/s — SM kernels cap at ~7.0
//           because stores pay L2 fill + dirty-writeback through the LTS)
//   node B: clock-keeper, CONCURRENT with A — one warp polling %globaltimer
//           for a fixed 100us so SM clocks don't park while the CE works.
//   node C: scatter (depends on A and B) — 3072 stores at full clock.

#define ENTITIES_N  100000
#define RELATIONS_N 1000
#define WIDTH       201000
#define BATCH       1024

// Wall-clock bounded spin: always shorter than the ~104us memset, regardless
// of DVFS state. No memory traffic, no output.
__global__ void clock_keeper()
{
    unsigned long long start, now;
    asm volatile("mov.u64 %0, %%globaltimer;" : "=l"(start));
    do {
        asm volatile("mov.u64 %0, %%globaltimer;" : "=l"(now));
    } while (now - start < 100000ULL);   // 100 us
}

__global__ void __launch_bounds__(256) scatter_ones(
    const int* __restrict__ hID,
    const int* __restrict__ rID,
    const int* __restrict__ tID,
    float* __restrict__ out)
{
    const unsigned tid = blockIdx.x * 256u + threadIdx.x;   // [0, 4096)
    const unsigned row = tid >> 2;
    const unsigned j   = tid & 3u;
    if (j == 3u) return;   // 3 stores per row

    const int* src = (j == 0) ? hID : (j == 1) ? rID : tID;
    const unsigned off = (j == 0) ? 0u
                       : (j == 1) ? (unsigned)ENTITIES_N
                                  : (unsigned)(ENTITIES_N + RELATIONS_N);

    const unsigned col = off + (unsigned)__ldg(&src[row]);
    out[(size_t)row * WIDTH + col] = 1.0f;
}

extern "C" void kernel_launch(void* const* d_in, const int* in_sizes, int n_in,
                              void* d_out, int out_size) {
    const int* hID = (const int*)d_in[1];
    const int* rID = (const int*)d_in[2];
    const int* tID = (const int*)d_in[3];
    float* out = (float*)d_out;

    // One-time side stream + events (host-side objects only; no device mem).
    static cudaStream_t side = nullptr;
    static cudaEvent_t evFork = nullptr, evJoin = nullptr;
    if (!side) {
        cudaStreamCreateWithFlags(&side, cudaStreamNonBlocking);
        cudaEventCreateWithFlags(&evFork, cudaEventDisableTiming);
        cudaEventCreateWithFlags(&evJoin, cudaEventDisableTiming);
    }

    // Fork: keeper runs concurrently with the memset.
    cudaEventRecord(evFork, 0);
    cudaStreamWaitEvent(side, evFork, 0);
    clock_keeper<<<1, 32, 0, side>>>();
    cudaEventRecord(evJoin, side);

    // Bulk zero on the CE fill path.
    cudaMemsetAsync(d_out, 0, (size_t)out_size * sizeof(float), 0);

    // Join, then scatter at (hopefully) unparked clocks.
    cudaStreamWaitEvent(0, evJoin, 0);
    scatter_ones<<<16, 256>>>(hID, rID, tID, out);
}